// round 11
// baseline (speedup 1.0000x reference)
#include <cuda_runtime.h>
#include <cstdint>

#define TPB 512
#define RPB 1024                 // rows per CTA (2 per thread)
#define XF  (RPB * 10)           // 10240 floats = 40960 B

__global__ void __launch_bounds__(TPB) encoder_stage_tab_kernel(
    const float* __restrict__ x,   // [N,10]
    const float* __restrict__ t,   // [N,1]
    const float* __restrict__ y,   // [N,1]
    const float* __restrict__ w,   // [2048]
    const float* __restrict__ b,   // [2048]
    float* __restrict__ out,       // [N,1]
    int n)
{
    __shared__ float  sx[XF];      // 40 KB x slab
    __shared__ float2 swb[2048];   // 16 KB interleaved (w,b)

    const int tid  = threadIdx.x;
    const int row0 = blockIdx.x * RPB;
    if (row0 >= n) return;

    // ---- 1) x slab via cp.async: coalesced, no register round trip ----
    const int nrows = min(RPB, n - row0);
    const int nf    = nrows * 10;
    const int nf4   = nf >> 2;
    const float* xs = x + (size_t)row0 * 10;
    uint32_t sb = (uint32_t)__cvta_generic_to_shared(sx);
    #pragma unroll 5
    for (int k = tid; k < nf4; k += TPB)
        asm volatile("cp.async.cg.shared.global [%0], [%1], 16;\n"
                     :: "r"(sb + k * 16), "l"((const float4*)xs + k));
    for (int k = (nf4 << 2) + tid; k < nf; k += TPB)   // generic-n tail
        sx[k] = xs[k];
    asm volatile("cp.async.commit_group;\n");

    // ---- 2) (w,b) table: exactly one float4 of each per thread ----
    {
        float4 wv = __ldg((const float4*)w + tid);   // tid in [0,512)
        float4 bv = __ldg((const float4*)b + tid);
        swb[4 * tid + 0] = make_float2(wv.x, bv.x);
        swb[4 * tid + 1] = make_float2(wv.y, bv.y);
        swb[4 * tid + 2] = make_float2(wv.z, bv.z);
        swb[4 * tid + 3] = make_float2(wv.w, bv.w);
    }

    // ---- 3) early-issue t/y (overlap with staging latency) ----
    const int i0 = row0 + 2 * tid;
    float2 tv = make_float2(0.f, 0.f), yv = make_float2(0.f, 0.f);
    const bool full_pair = (i0 + 1 < n);
    if (full_pair) {
        tv = *(const float2*)(t + i0);   // i0 even -> 8B aligned
        yv = *(const float2*)(y + i0);
    } else if (i0 < n) {
        tv.x = t[i0];
        yv.x = y[i0];
    }

    asm volatile("cp.async.wait_group 0;\n" ::: "memory");
    __syncthreads();

    if (i0 >= n) return;

    // ---- 4) index build: 5 x LDS.128 over this thread's 20 floats ----
    const float* xr = sx + 2 * tid * 10;
    int idx0 = 0, idx1 = 0;
    #pragma unroll
    for (int q = 0; q < 5; ++q) {
        float4 f = *(const float4*)(xr + 4 * q);
        float e[4] = {f.x, f.y, f.z, f.w};
        #pragma unroll
        for (int c = 0; c < 4; ++c) {
            int fi = 4 * q + c;
            int bit = (e[c] != 0.0f) ? 1 : 0;
            if (fi < 10) idx0 = (idx0 << 1) | bit;
            else         idx1 = (idx1 << 1) | bit;
        }
    }
    idx0 |= ((tv.x != 0.0f) ? 1 : 0) << 10;
    idx1 |= ((tv.y != 0.0f) ? 1 : 0) << 10;

    // ---- 5) table gather (LDS.64) + FMA + coalesced STG.64 ----
    float2 wb0 = swb[idx0];
    if (full_pair) {
        float2 wb1 = swb[idx1];
        float2 o;
        o.x = fmaf(yv.x, wb0.x, wb0.y);
        o.y = fmaf(yv.y, wb1.x, wb1.y);
        *(float2*)(out + i0) = o;
    } else {
        out[i0] = fmaf(yv.x, wb0.x, wb0.y);
    }
}

extern "C" void kernel_launch(void* const* d_in, const int* in_sizes, int n_in,
                              void* d_out, int out_size)
{
    const float* x = (const float*)d_in[0];
    const float* t = (const float*)d_in[1];
    const float* y = (const float*)d_in[2];
    const float* w = (const float*)d_in[3];
    const float* b = (const float*)d_in[4];
    float* out = (float*)d_out;

    int n = in_sizes[1];
    int blocks = (n + RPB - 1) / RPB;
    encoder_stage_tab_kernel<<<blocks, TPB>>>(x, t, y, w, b, out, n);
}

// round 12
// speedup vs baseline: 1.1345x; 1.1345x over previous
#include <cuda_runtime.h>
#include <cstdint>

#define TPB 256

__global__ void __launch_bounds__(TPB) encoder_persist_tab_kernel(
    const float* __restrict__ x,   // [N,10]
    const float* __restrict__ t,   // [N,1]
    const float* __restrict__ y,   // [N,1]
    const float* __restrict__ w,   // [2048]
    const float* __restrict__ b,   // [2048]
    float* __restrict__ out,       // [N,1]
    int n)
{
    __shared__ float2 swb[2048];   // interleaved (w,b): 16 KB

    const int tid = threadIdx.x;

    // ---- build (w,b) table once per CTA ----
#pragma unroll
    for (int j = 0; j < 2; ++j) {
        int k = tid + j * TPB;                   // float4 index 0..511
        float4 wv = __ldg((const float4*)w + k);
        float4 bv = __ldg((const float4*)b + k);
        swb[4 * k + 0] = make_float2(wv.x, bv.x);
        swb[4 * k + 1] = make_float2(wv.y, bv.y);
        swb[4 * k + 2] = make_float2(wv.z, bv.z);
        swb[4 * k + 3] = make_float2(wv.w, bv.w);
    }
    __syncthreads();

    const int nth   = gridDim.x * TPB;
    const int nfull = n >> 1;                    // full row-pairs

    // odd final row (generic-n safety): one thread, scalar path
    if ((n & 1) && blockIdx.x == 0 && tid == 0) {
        const float* xr = x + (size_t)(n - 1) * 10;
        int idx = 0;
#pragma unroll
        for (int j = 0; j < 10; ++j)
            idx = (idx << 1) | (xr[j] != 0.f ? 1 : 0);
        idx |= (t[n - 1] != 0.f ? 1 : 0) << 10;
        float2 wb = swb[idx];
        out[n - 1] = fmaf(y[n - 1], wb.x, wb.y);
    }

    // ---- persistent grid-stride loop over row pairs (no barriers) ----
    for (int p = blockIdx.x * TPB + tid; p < nfull; p += nth) {
        const int i0 = p * 2;
        const float4* xv = (const float4*)(x + (size_t)i0 * 10);
        // 5 independent LDG.128 + 2 LDG.64, all front-batched
        float4 f0 = __ldg(xv + 0);
        float4 f1 = __ldg(xv + 1);
        float4 f2 = __ldg(xv + 2);
        float4 f3 = __ldg(xv + 3);
        float4 f4 = __ldg(xv + 4);
        float2 tv = __ldg((const float2*)(t + i0));
        float2 yv = __ldg((const float2*)(y + i0));

        const int idx0 =
            ((f0.x != 0.f) << 9) | ((f0.y != 0.f) << 8) |
            ((f0.z != 0.f) << 7) | ((f0.w != 0.f) << 6) |
            ((f1.x != 0.f) << 5) | ((f1.y != 0.f) << 4) |
            ((f1.z != 0.f) << 3) | ((f1.w != 0.f) << 2) |
            ((f2.x != 0.f) << 1) | ((f2.y != 0.f) << 0) |
            ((tv.x != 0.f) << 10);
        const int idx1 =
            ((f2.z != 0.f) << 9) | ((f2.w != 0.f) << 8) |
            ((f3.x != 0.f) << 7) | ((f3.y != 0.f) << 6) |
            ((f3.z != 0.f) << 5) | ((f3.w != 0.f) << 4) |
            ((f4.x != 0.f) << 3) | ((f4.y != 0.f) << 2) |
            ((f4.z != 0.f) << 1) | ((f4.w != 0.f) << 0) |
            ((tv.y != 0.f) << 10);

        float2 wb0 = swb[idx0];
        float2 wb1 = swb[idx1];
        float2 o;
        o.x = fmaf(yv.x, wb0.x, wb0.y);
        o.y = fmaf(yv.y, wb1.x, wb1.y);
        *(float2*)(out + i0) = o;
    }
}

extern "C" void kernel_launch(void* const* d_in, const int* in_sizes, int n_in,
                              void* d_out, int out_size)
{
    const float* x = (const float*)d_in[0];
    const float* t = (const float*)d_in[1];
    const float* y = (const float*)d_in[2];
    const float* b_w = (const float*)d_in[3];
    const float* b_b = (const float*)d_in[4];
    float* out = (float*)d_out;

    int n = in_sizes[1];
    int nfull = n >> 1;
    int blocks = 8 * 152;                         // one full resident wave on GB300
    int needed = (nfull + TPB - 1) / TPB;
    if (blocks > needed) blocks = needed;
    if (blocks < 1) blocks = 1;
    encoder_persist_tab_kernel<<<blocks, TPB>>>(x, t, y, b_w, b_b, out, n);
}